// round 12
// baseline (speedup 1.0000x reference)
#include <cuda_runtime.h>

// Problem shape (fixed by the dataset)
#define W_  1920
#define H_  1080
constexpr int HW  = H_ * W_;       // 2,073,600
constexpr int N   = 4 * HW;        // 8,294,400 (B = 4)
constexpr int B_  = 4;

// Padded point-scatter buffer P (per batch): indexed by floor-target (x0,y0),
// x0 in [-1, W-1], y0 in [-1, H-1] -> stored at [y0+1][x0+1].
constexpr int PS  = 1924;          // padded row stride (>= W_+1, %4==0)
constexpr int PR  = H_ + 1;        // 1081 padded rows
constexpr int PB  = PR * PS;       // ints per batch = 2,079,844
constexpr int PB4 = PB / 4;        // int4s per batch = 519,961 (< HW)
constexpr int PT  = B_ * PB;

// Scratch (cudaMalloc forbidden -> static device globals, zero-initialized at load).
// INVARIANT at entry of every kernel_launch: each batch's P slice is all-zero
// (re-zeroed by that batch's k_accum, after k_dilate consumed it); acc is
// overwritten (zeroed) by k_depth; dbuf fully overwritten by k_dilate.
__device__ __align__(16) int    g_P[PT];
__device__ __align__(16) int    g_dbuf[N];
__device__ __align__(16) float4 g_acc[N];    // AoS: {weight, c0, c1, c2}

// One 16-byte vector reduction instead of 4 scalar float atomics.
__device__ __forceinline__ void red_add_v4(float4* p, float a, float b, float c, float d)
{
    asm volatile("red.global.add.v4.f32 [%0], {%1, %2, %3, %4};"
                 :: "l"(p), "f"(a), "f"(b), "f"(c), "f"(d) : "memory");
}

// Streaming (evict-first) loads for read-once inputs.
__device__ __forceinline__ float2 ldcs_f2(const float2* p)
{
    float2 r;
    asm volatile("ld.global.cs.v2.f32 {%0, %1}, [%2];"
                 : "=f"(r.x), "=f"(r.y) : "l"(p));
    return r;
}
__device__ __forceinline__ float ldcs_f(const float* p)
{
    float r;
    asm volatile("ld.global.cs.f32 %0, [%1];" : "=f"(r) : "l"(p));
    return r;
}

__device__ __forceinline__ int depth_key(float fx, float fy)
{
    // round-half-even (matches jnp.round), IEEE sqrt regardless of fast-math
    return __float2int_rn(__fsqrt_rn(fx * fx + fy * fy) * 1000.0f);
}

// ---------------------------------------------------------------------------
// Pass 1 (per batch): point scatter-max into padded P (ONE RED per source)
// + fused acc zeroing (keeps acc L2-warm for the accumulate pass).
// ---------------------------------------------------------------------------
__global__ void __launch_bounds__(256) k_depth(const float2* __restrict__ flow,
                                               float4* __restrict__ acc,
                                               int* __restrict__ P)
{
    int i = blockIdx.x * blockDim.x + threadIdx.x;
    if (i >= HW) return;

    acc[i] = make_float4(0.f, 0.f, 0.f, 0.f);   // fused zeroing (STG.128)

    int h = i / W_;
    int w = i - h * W_;

    float2 f = ldcs_f2(flow + i);
    int x0 = (int)floorf((float)w + f.x);
    int y0 = (int)floorf((float)h + f.y);

    if (x0 >= -1 && x0 < W_ && y0 >= -1 && y0 < H_) {
        int d = depth_key(f.x, f.y);
        atomicMax(&P[(y0 + 1) * PS + (x0 + 1)], d);
    }
}

// ---------------------------------------------------------------------------
// Pass 1.5 (per batch): 2x2 max-dilation P -> dbuf (coalesced, 4 out/thread).
// dbuf[ty][tx] = max(Pp[ty][tx], Pp[ty][tx+1], Pp[ty+1][tx], Pp[ty+1][tx+1]).
// Reproduces the reference scatter-max dbuf EXACTLY (init 0 included).
// ---------------------------------------------------------------------------
__global__ void __launch_bounds__(256) k_dilate(const int* __restrict__ P,
                                                int* __restrict__ dbuf)
{
    int t = blockIdx.x * blockDim.x + threadIdx.x;
    if (t >= HW / 4) return;

    int i  = t * 4;                 // first output pixel (W_%4==0 -> same row)
    int ty = i / W_;
    int tx = i - ty * W_;           // multiple of 4

    const int* r0 = P + ty * PS + tx;
    const int* r1 = r0 + PS;

    int4 A  = *reinterpret_cast<const int4*>(r0);   // 16B aligned (PS%4==0)
    int4 Bv = *reinterpret_cast<const int4*>(r1);
    int  a4 = r0[4];
    int  b4 = r1[4];

    int4 o;
    o.x = max(max(A.x, A.y), max(Bv.x, Bv.y));
    o.y = max(max(A.y, A.z), max(Bv.y, Bv.z));
    o.z = max(max(A.z, A.w), max(Bv.z, Bv.w));
    o.w = max(max(A.w, a4),  max(Bv.w, b4));

    reinterpret_cast<int4*>(dbuf)[t] = o;
}

// ---------------------------------------------------------------------------
// Pass 2 helper: depth-test + accumulate both x-corners on one row.
// ONE 16B gather covers both corners when they share a 16B window (75%).
// (R8/R10 shape -- empirically optimal.)
// ---------------------------------------------------------------------------
__device__ __forceinline__ void accum_row(const int* __restrict__ rowd,
                                          float4* __restrict__ rowa,
                                          int x0, int d, float wl, float wr,
                                          float v0, float v1, float v2)
{
    bool vx0 = (x0 >= 0)     & (x0 < W_);
    bool vx1 = (x0 + 1 >= 0) & (x0 + 1 < W_);
    if (!vx0 && !vx1) return;

    int d0 = -1, d1 = -1;
    int r = x0 & 3;
    if (vx0 && vx1 && r != 3) {
        int4 q = __ldg(reinterpret_cast<const int4*>(rowd) + (x0 >> 2));  // 16B aligned
        d0 = (r == 0) ? q.x : (r == 1) ? q.y : q.z;
        d1 = (r == 0) ? q.y : (r == 1) ? q.z : q.w;
    } else {
        if (vx0) d0 = __ldg(rowd + x0);
        if (vx1) d1 = __ldg(rowd + x0 + 1);
    }
    // d >= 0 always, so sentinel -1 never matches
    if (d0 == d && wl != 0.0f) red_add_v4(rowa + x0,     wl, wl * v0, wl * v1, wl * v2);
    if (d1 == d && wr != 0.0f) red_add_v4(rowa + x0 + 1, wr, wr * v0, wr * v1, wr * v2);
}

// ---------------------------------------------------------------------------
// Pass 2 (per batch): accumulate depth-test winners + re-zero this batch's P.
// ---------------------------------------------------------------------------
__global__ void __launch_bounds__(256) k_accum(const float* __restrict__ im0,
                                               const float2* __restrict__ flow,
                                               const int* __restrict__ dbuf,
                                               float4* __restrict__ acc,
                                               int* __restrict__ P)
{
    int i = blockIdx.x * blockDim.x + threadIdx.x;
    if (i >= HW) return;

    // fused P re-zeroing (dilate already consumed it; PB4 < HW)
    if (i < PB4)
        reinterpret_cast<int4*>(P)[i] = make_int4(0, 0, 0, 0);

    int h = i / W_;
    int w = i - h * W_;

    float2 f = ldcs_f2(flow + i);
    float x = (float)w + f.x;
    float y = (float)h + f.y;
    float x0f = floorf(x);
    float y0f = floorf(y);
    float ax = x - x0f;
    float ay = y - y0f;
    int x0 = (int)x0f;
    int y0 = (int)y0f;
    int d  = depth_key(f.x, f.y);

    // source pixel values (3 channels, planar, coalesced, streaming)
    float v0 = ldcs_f(im0 + i);
    float v1 = ldcs_f(im0 + HW + i);
    float v2 = ldcs_f(im0 + 2 * HW + i);

    float wx1 = ax, wx0 = 1.0f - ax;
    float wy1 = ay, wy0 = 1.0f - ay;

    if (y0 >= 0 && y0 < H_)
        accum_row(dbuf + y0 * W_, acc + y0 * W_, x0, d,
                  wx0 * wy0, wx1 * wy0, v0, v1, v2);
    if (y0 + 1 >= 0 && y0 + 1 < H_)
        accum_row(dbuf + (y0 + 1) * W_, acc + (y0 + 1) * W_, x0, d,
                  wx0 * wy1, wx1 * wy1, v0, v1, v2);
}

// ---------------------------------------------------------------------------
// Pass 3 (per batch): normalize (4 pixels/thread).
// out[c][h][w] = acc.c / max(acc.w, eps)
// ---------------------------------------------------------------------------
__global__ void __launch_bounds__(256) k_norm(const float4* __restrict__ acc,
                                              float* __restrict__ out)
{
    int t = blockIdx.x * blockDim.x + threadIdx.x;
    if (t >= HW / 4) return;

    int i = t * 4;

    float4 a0 = acc[i];
    float4 a1 = acc[i + 1];
    float4 a2 = acc[i + 2];
    float4 a3 = acc[i + 3];

    float r0 = 1.0f / fmaxf(a0.x, 1e-5f);
    float r1 = 1.0f / fmaxf(a1.x, 1e-5f);
    float r2 = 1.0f / fmaxf(a2.x, 1e-5f);
    float r3 = 1.0f / fmaxf(a3.x, 1e-5f);

    float* dst = out + i;                          // i % 4 == 0 -> 16B aligned
    reinterpret_cast<float4*>(dst)[0]          = make_float4(a0.y * r0, a1.y * r1, a2.y * r2, a3.y * r3);
    reinterpret_cast<float4*>(dst + HW)[0]     = make_float4(a0.z * r0, a1.z * r1, a2.z * r2, a3.z * r3);
    reinterpret_cast<float4*>(dst + 2 * HW)[0] = make_float4(a0.w * r0, a1.w * r1, a2.w * r2, a3.w * r3);
}

// ---------------------------------------------------------------------------
// Two-stream fork-join pipeline (graph-capturable):
//   stream0 (capture stream): depth(0..3) then accum(0..3)  -- lane/atomic bound
//   s2:                        dilate(b) after depth(b); norm(b) after accum(b)
//                              -- DRAM-bound, hidden under stream0's lane work
// ---------------------------------------------------------------------------
extern "C" void kernel_launch(void* const* d_in, const int* in_sizes, int n_in,
                              void* d_out, int out_size)
{
    const float*  im0  = (const float*)d_in[0];   // [B,C,H,W] float32
    const float2* flow = (const float2*)d_in[1];  // [B,H,W,2] float32
    float*        out  = (float*)d_out;           // [B,C,H,W] float32

    // One-time handle creation (first call = uncaptured correctness run).
    static cudaStream_t s2 = nullptr;
    static cudaEvent_t  evD[B_], evL[B_], evA[B_], evN[B_];
    if (s2 == nullptr) {
        cudaStreamCreateWithFlags(&s2, cudaStreamNonBlocking);
        for (int b = 0; b < B_; b++) {
            cudaEventCreateWithFlags(&evD[b], cudaEventDisableTiming);
            cudaEventCreateWithFlags(&evL[b], cudaEventDisableTiming);
            cudaEventCreateWithFlags(&evA[b], cudaEventDisableTiming);
            cudaEventCreateWithFlags(&evN[b], cudaEventDisableTiming);
        }
    }

    float4* acc_base; int* dbuf_base; int* P_base;
    cudaGetSymbolAddress((void**)&acc_base,  g_acc);
    cudaGetSymbolAddress((void**)&dbuf_base, g_dbuf);
    cudaGetSymbolAddress((void**)&P_base,    g_P);

    const int T  = 256;
    const int G  = (HW + T - 1) / T;        // 8100
    const int G4 = (HW / 4 + T - 1) / T;    // 2025

    // Phase A: depth chain on stream0; dilate(b) forked onto s2 after depth(b).
    for (int b = 0; b < B_; b++) {
        const float2* flow_b = flow + (size_t)b * HW;
        float4*       acc_b  = acc_base  + (size_t)b * HW;
        int*          dbuf_b = dbuf_base + (size_t)b * HW;
        int*          P_b    = P_base    + (size_t)b * PB;

        k_depth<<<G, T>>>(flow_b, acc_b, P_b);
        cudaEventRecord(evD[b], 0);
        cudaStreamWaitEvent(s2, evD[b], 0);
        k_dilate<<<G4, T, 0, s2>>>(P_b, dbuf_b);
        cudaEventRecord(evL[b], s2);
    }

    // Phase B: accum chain on stream0 (waits per-batch dilate); norm forked to s2.
    for (int b = 0; b < B_; b++) {
        const float2* flow_b = flow + (size_t)b * HW;
        const float*  im0_b  = im0  + (size_t)b * 3 * HW;
        float4*       acc_b  = acc_base  + (size_t)b * HW;
        int*          dbuf_b = dbuf_base + (size_t)b * HW;
        int*          P_b    = P_base    + (size_t)b * PB;
        float*        out_b  = out + (size_t)b * 3 * HW;

        cudaStreamWaitEvent(0, evL[b], 0);
        k_accum<<<G, T>>>(im0_b, flow_b, dbuf_b, acc_b, P_b);
        cudaEventRecord(evA[b], 0);
        cudaStreamWaitEvent(s2, evA[b], 0);
        k_norm<<<G4, T, 0, s2>>>(acc_b, out_b);
        cudaEventRecord(evN[b], s2);
    }

    // Join: stream0 completes only after all norms (harness syncs/captures stream0).
    for (int b = 0; b < B_; b++)
        cudaStreamWaitEvent(0, evN[b], 0);

    (void)in_sizes; (void)n_in; (void)out_size;
}

// round 13
// speedup vs baseline: 1.0483x; 1.0483x over previous
#include <cuda_runtime.h>

// Problem shape (fixed by the dataset)
#define W_  1920
#define H_  1080
#define B_  4
#define C_  3
constexpr int HW = H_ * W_;        // 2,073,600
constexpr int N  = B_ * HW;        // 8,294,400

// Padded point-scatter buffer P: indexed by floor-target (x0,y0) with
// x0 in [-1, W-1], y0 in [-1, H-1]  -> stored at [y0+1][x0+1].
constexpr int PS  = 1924;              // padded row stride (>= W_+1, %4==0)
constexpr int PR  = H_ + 1;            // 1081 padded rows
constexpr int PB  = PR * PS;           // ints per batch
constexpr int PT  = B_ * PB;           // total ints
constexpr int PT4 = PT / 4;            // total int4s

// Scratch (cudaMalloc forbidden -> static device globals, zero-initialized at load).
// INVARIANT at entry of every kernel_launch: g_P all-zero (re-zeroed by k_accum
// each call, AFTER k_dilate consumed it); g_acc overwritten (zeroed) by k_depth;
// g_dbuf fully overwritten by k_dilate (no init needed).
__device__ __align__(16) int    g_P[PT];     // padded floor-target max-key buffer
__device__ __align__(16) int    g_dbuf[N];   // dilated depth buffer (== reference dbuf)
__device__ __align__(16) float4 g_acc[N];    // AoS: {weight, c0, c1, c2} per pixel

// One 16-byte vector reduction instead of 4 scalar float atomics.
__device__ __forceinline__ void red_add_v4(float4* p, float a, float b, float c, float d)
{
    asm volatile("red.global.add.v4.f32 [%0], {%1, %2, %3, %4};"
                 :: "l"(p), "f"(a), "f"(b), "f"(c), "f"(d) : "memory");
}

// Streaming (evict-first) loads/stores for read-once / write-once traffic.
__device__ __forceinline__ float2 ldcs_f2(const float2* p)
{
    float2 r;
    asm volatile("ld.global.cs.v2.f32 {%0, %1}, [%2];"
                 : "=f"(r.x), "=f"(r.y) : "l"(p));
    return r;
}
__device__ __forceinline__ float ldcs_f(const float* p)
{
    float r;
    asm volatile("ld.global.cs.f32 %0, [%1];" : "=f"(r) : "l"(p));
    return r;
}
__device__ __forceinline__ float4 ldcs_f4(const float4* p)
{
    float4 r;
    asm volatile("ld.global.cs.v4.f32 {%0, %1, %2, %3}, [%4];"
                 : "=f"(r.x), "=f"(r.y), "=f"(r.z), "=f"(r.w) : "l"(p));
    return r;
}
__device__ __forceinline__ void stcs_f4(float4* p, float4 v)
{
    asm volatile("st.global.cs.v4.f32 [%0], {%1, %2, %3, %4};"
                 :: "l"(p), "f"(v.x), "f"(v.y), "f"(v.z), "f"(v.w) : "memory");
}
__device__ __forceinline__ void stcs_zero4(int4* p)
{
    asm volatile("st.global.cs.v4.b32 [%0], {%1, %1, %1, %1};"
                 :: "l"(p), "r"(0) : "memory");
}

__device__ __forceinline__ int depth_key(float fx, float fy)
{
    // round-half-even (matches jnp.round), IEEE sqrt regardless of fast-math
    return __float2int_rn(__fsqrt_rn(fx * fx + fy * fy) * 1000.0f);
}

// ---------------------------------------------------------------------------
// Pass 1: point scatter-max into padded P (ONE scalar RED per source) + fused
// g_acc zeroing (placement is load-bearing: keeps acc L2-warm for pass 3;
// these stores intentionally use default policy so the lines STAY in L2).
// ---------------------------------------------------------------------------
__global__ void __launch_bounds__(256) k_depth(const float2* __restrict__ flow)
{
    int i = blockIdx.x * blockDim.x + threadIdx.x;
    if (i >= N) return;

    g_acc[i] = make_float4(0.f, 0.f, 0.f, 0.f);   // fused zeroing (STG.128, L2-resident)

    int b = i / HW;
    int p = i - b * HW;
    int h = p / W_;
    int w = p - h * W_;

    float2 f = ldcs_f2(flow + i);
    int x0 = (int)floorf((float)w + f.x);
    int y0 = (int)floorf((float)h + f.y);

    if (x0 >= -1 && x0 < W_ && y0 >= -1 && y0 < H_) {
        int d = depth_key(f.x, f.y);
        atomicMax(&g_P[b * PB + (y0 + 1) * PS + (x0 + 1)], d);
    }
}

// ---------------------------------------------------------------------------
// Pass 1.5: 2x2 max-dilation P -> dbuf (coalesced, 4 outputs/thread).
// dbuf[ty][tx] = max(Pp[ty][tx], Pp[ty][tx+1], Pp[ty+1][tx], Pp[ty+1][tx+1]).
// Reproduces the reference scatter-max dbuf EXACTLY (init 0 included).
// ---------------------------------------------------------------------------
__global__ void __launch_bounds__(256) k_dilate()
{
    int t = blockIdx.x * blockDim.x + threadIdx.x;
    if (t >= N / 4) return;

    int i  = t * 4;                 // first output pixel (W_%4==0 -> same row)
    int b  = i / HW;
    int p  = i - b * HW;
    int ty = p / W_;
    int tx = p - ty * W_;           // multiple of 4

    const int* Pp = g_P + b * PB;
    const int* r0 = Pp + ty * PS + tx;
    const int* r1 = r0 + PS;

    int4 A  = *reinterpret_cast<const int4*>(r0);   // 16B aligned (PS%4==0)
    int4 Bv = *reinterpret_cast<const int4*>(r1);
    int  a4 = r0[4];
    int  b4 = r1[4];

    int4 o;
    o.x = max(max(A.x, A.y), max(Bv.x, Bv.y));
    o.y = max(max(A.y, A.z), max(Bv.y, Bv.z));
    o.z = max(max(A.z, A.w), max(Bv.z, Bv.w));
    o.w = max(max(A.w, a4),  max(Bv.w, b4));

    reinterpret_cast<int4*>(g_dbuf)[t] = o;
}

// ---------------------------------------------------------------------------
// Pass 2 helper: depth-test + accumulate both x-corners on one row.
// ONE 16B gather covers both corners when they share a 16B window (75%).
// (R8/R10 shape -- empirically optimal; restructuring attempts regressed.)
// ---------------------------------------------------------------------------
__device__ __forceinline__ void accum_row(const int* __restrict__ rowd,
                                          float4* __restrict__ rowa,
                                          int x0, int d, float wl, float wr,
                                          float v0, float v1, float v2)
{
    bool vx0 = (x0 >= 0)     & (x0 < W_);
    bool vx1 = (x0 + 1 >= 0) & (x0 + 1 < W_);
    if (!vx0 && !vx1) return;

    int d0 = -1, d1 = -1;
    int r = x0 & 3;
    if (vx0 && vx1 && r != 3) {
        int4 q = __ldg(reinterpret_cast<const int4*>(rowd) + (x0 >> 2));  // 16B aligned
        d0 = (r == 0) ? q.x : (r == 1) ? q.y : q.z;
        d1 = (r == 0) ? q.y : (r == 1) ? q.z : q.w;
    } else {
        if (vx0) d0 = __ldg(rowd + x0);
        if (vx1) d1 = __ldg(rowd + x0 + 1);
    }
    // d >= 0 always, so sentinel -1 never matches
    if (d0 == d && wl != 0.0f) red_add_v4(rowa + x0,     wl, wl * v0, wl * v1, wl * v2);
    if (d1 == d && wr != 0.0f) red_add_v4(rowa + x0 + 1, wr, wr * v0, wr * v1, wr * v2);
}

// ---------------------------------------------------------------------------
// Pass 2: accumulate depth-test winners, ONE vec4 reduction per winning corner.
// Also re-zeroes g_P for the next call with EVICT-FIRST stores (the zero lines
// are dead until the next replay -- keep them out of g_acc's L2 space).
// ---------------------------------------------------------------------------
__global__ void __launch_bounds__(256) k_accum(const float* __restrict__ im0,
                                               const float2* __restrict__ flow)
{
    int i = blockIdx.x * blockDim.x + threadIdx.x;
    if (i >= N) return;

    // fused P re-zeroing (deterministic: loader zeros on first call, these
    // stores on all subsequent calls; PT4 < N so first PT4 threads cover it)
    if (i < PT4)
        stcs_zero4(reinterpret_cast<int4*>(g_P) + i);

    int b = i / HW;
    int p = i - b * HW;
    int h = p / W_;
    int w = p - h * W_;

    float2 f = ldcs_f2(flow + i);
    float x = (float)w + f.x;
    float y = (float)h + f.y;
    float x0f = floorf(x);
    float y0f = floorf(y);
    float ax = x - x0f;
    float ay = y - y0f;
    int x0 = (int)x0f;
    int y0 = (int)y0f;
    int d  = depth_key(f.x, f.y);

    // source pixel values (3 channels, planar, coalesced, streaming)
    const float* src = im0 + (size_t)b * 3 * HW + p;
    float v0 = ldcs_f(src);
    float v1 = ldcs_f(src + HW);
    float v2 = ldcs_f(src + 2 * HW);

    float wx1 = ax, wx0 = 1.0f - ax;
    float wy1 = ay, wy0 = 1.0f - ay;

    const int* bufb = g_dbuf + b * HW;
    float4*    accb = g_acc  + b * HW;
    if (y0 >= 0 && y0 < H_)
        accum_row(bufb + y0 * W_, accb + y0 * W_, x0, d,
                  wx0 * wy0, wx1 * wy0, v0, v1, v2);
    if (y0 + 1 >= 0 && y0 + 1 < H_)
        accum_row(bufb + (y0 + 1) * W_, accb + (y0 + 1) * W_, x0, d,
                  wx0 * wy1, wx1 * wy1, v0, v1, v2);
}

// ---------------------------------------------------------------------------
// Pass 3: normalize (4 pixels/thread). Read-once acc loads and write-once
// output stores are streaming (evict-first).
// out[b][c][h][w] = acc.c / max(acc.w, eps)
// ---------------------------------------------------------------------------
__global__ void __launch_bounds__(256) k_norm(float* __restrict__ out)
{
    int t = blockIdx.x * blockDim.x + threadIdx.x;
    if (t >= N / 4) return;

    int i = t * 4;            // first pixel of this group (HW % 4 == 0 -> same b)
    int b = i / HW;
    int p = i - b * HW;

    float4 a0 = ldcs_f4(g_acc + i);
    float4 a1 = ldcs_f4(g_acc + i + 1);
    float4 a2 = ldcs_f4(g_acc + i + 2);
    float4 a3 = ldcs_f4(g_acc + i + 3);

    float r0 = 1.0f / fmaxf(a0.x, 1e-5f);
    float r1 = 1.0f / fmaxf(a1.x, 1e-5f);
    float r2 = 1.0f / fmaxf(a2.x, 1e-5f);
    float r3 = 1.0f / fmaxf(a3.x, 1e-5f);

    float* dst = out + (size_t)b * 3 * HW + p;    // p % 4 == 0 -> 16B aligned
    stcs_f4(reinterpret_cast<float4*>(dst),          make_float4(a0.y * r0, a1.y * r1, a2.y * r2, a3.y * r3));
    stcs_f4(reinterpret_cast<float4*>(dst + HW),     make_float4(a0.z * r0, a1.z * r1, a2.z * r2, a3.z * r3));
    stcs_f4(reinterpret_cast<float4*>(dst + 2 * HW), make_float4(a0.w * r0, a1.w * r1, a2.w * r2, a3.w * r3));
}

// ---------------------------------------------------------------------------
extern "C" void kernel_launch(void* const* d_in, const int* in_sizes, int n_in,
                              void* d_out, int out_size)
{
    const float*  im0  = (const float*)d_in[0];   // [B,C,H,W] float32
    const float2* flow = (const float2*)d_in[1];  // [B,H,W,2] float32
    float*        out  = (float*)d_out;           // [B,C,H,W] float32

    const int T = 256;

    k_depth <<<(N + T - 1) / T, T>>>(flow);
    k_dilate<<<(N / 4 + T - 1) / T, T>>>();
    k_accum <<<(N + T - 1) / T, T>>>(im0, flow);
    k_norm  <<<(N / 4 + T - 1) / T, T>>>(out);

    (void)in_sizes; (void)n_in; (void)out_size;
}